// round 3
// baseline (speedup 1.0000x reference)
#include <cuda_runtime.h>
#include <math.h>

#define B_   16
#define T_   512
#define C_   1024
#define H_   16
#define D_   64
#define M_   (B_ * T_)      // 8192 rows for all GEMMs
#define K_   C_             // 1024

// ---------------- scratch (no allocations allowed) ----------------
__device__ float g_q[B_ * H_ * T_ * D_];     // (B,H,T,D)
__device__ float g_k[B_ * H_ * T_ * D_];
__device__ float g_v[B_ * H_ * T_ * D_];
__device__ float g_att[B_ * T_ * C_];        // (B,T,C) pre-output-proj

// =================================================================
// GEMM: out[m][n] = sum_k A[m][k] * W[n][k] + bias[n]
// qkv_scatter==1: write to (B,H,T,D) layout; else row-major [M, C]
// BM=BN=128, BK=8, 8x8 per thread, 256 threads.
// =================================================================
#define BM 128
#define BN 128
#define BKg 8

__global__ __launch_bounds__(256) void gemm_xwT(
    const float* __restrict__ A, const float* __restrict__ W,
    const float* __restrict__ bias, float* __restrict__ out,
    int qkv_scatter)
{
    __shared__ float As[BKg][BM];
    __shared__ float Bs[BKg][BN];

    const int tid = threadIdx.x;
    const int m0 = blockIdx.y * BM;
    const int n0 = blockIdx.x * BN;
    const int ty = tid >> 4;       // 0..15
    const int tx = tid & 15;       // 0..15

    const int lrow = tid >> 1;         // 0..127
    const int lcol = (tid & 1) * 4;    // 0 or 4

    float acc[8][8];
#pragma unroll
    for (int i = 0; i < 8; i++)
#pragma unroll
        for (int j = 0; j < 8; j++) acc[i][j] = 0.0f;

    const float* Aptr = A + (long)(m0 + lrow) * K_ + lcol;
    const float* Wptr = W + (long)(n0 + lrow) * K_ + lcol;

    for (int k0 = 0; k0 < K_; k0 += BKg) {
        float4 av = *(const float4*)(Aptr + k0);
        float4 wv = *(const float4*)(Wptr + k0);
        As[lcol + 0][lrow] = av.x;
        As[lcol + 1][lrow] = av.y;
        As[lcol + 2][lrow] = av.z;
        As[lcol + 3][lrow] = av.w;
        Bs[lcol + 0][lrow] = wv.x;
        Bs[lcol + 1][lrow] = wv.y;
        Bs[lcol + 2][lrow] = wv.z;
        Bs[lcol + 3][lrow] = wv.w;
        __syncthreads();

#pragma unroll
        for (int k = 0; k < BKg; k++) {
            float4 a0 = *(const float4*)&As[k][ty * 8];
            float4 a1 = *(const float4*)&As[k][ty * 8 + 4];
            float4 b0 = *(const float4*)&Bs[k][tx * 8];
            float4 b1 = *(const float4*)&Bs[k][tx * 8 + 4];
            float a[8] = {a0.x, a0.y, a0.z, a0.w, a1.x, a1.y, a1.z, a1.w};
            float b[8] = {b0.x, b0.y, b0.z, b0.w, b1.x, b1.y, b1.z, b1.w};
#pragma unroll
            for (int i = 0; i < 8; i++)
#pragma unroll
                for (int j = 0; j < 8; j++)
                    acc[i][j] = fmaf(a[i], b[j], acc[i][j]);
        }
        __syncthreads();
    }

    // epilogue
#pragma unroll
    for (int i = 0; i < 8; i++) {
        int m = m0 + ty * 8 + i;
#pragma unroll
        for (int j = 0; j < 8; j++) {
            int n = n0 + tx * 8 + j;
            float v = acc[i][j] + bias[n];
            if (qkv_scatter) {
                int b = m >> 9;          // m / 512
                int t = m & 511;
                int h = n >> 6;          // n / 64
                int d = n & 63;
                out[(((b * H_ + h) * T_ + t) << 6) + d] = v;
            } else {
                out[(long)m * C_ + n] = v;
            }
        }
    }
}

// =================================================================
// Flash attention, fp32. One block = one (b,h) x 64-query tile.
// 256 threads (16x16), 4x4 micro-tile. Online softmax.
// smem: Qt[d][q], Kt[d][s], Vs[s][d], Pt[s][q], all [64][68].
// =================================================================
#define LDA 68
#define SMEM_ATTN (4 * 64 * LDA * (int)sizeof(float))

__global__ __launch_bounds__(256) void attn_kernel(const float* __restrict__ rpb)
{
    extern __shared__ float sm[];
    float* Qt = sm;                 // [64][LDA]  Qt[d][q]
    float* Kt = Qt + 64 * LDA;      // [64][LDA]  Kt[d][s]
    float* Vs = Kt + 64 * LDA;      // [64][LDA]  Vs[s][d]
    float* Pt = Vs + 64 * LDA;      // [64][LDA]  Pt[s][q]

    const int bh = blockIdx.y;              // 0..255
    const int h  = bh & (H_ - 1);
    const int qb = blockIdx.x;              // 0..7

    const float* qptr = g_q + (long)bh * T_ * D_;
    const float* kptr = g_k + (long)bh * T_ * D_;
    const float* vptr = g_v + (long)bh * T_ * D_;
    const float* bptr = rpb + (long)h * T_ * T_;

    const int tid = threadIdx.x;
    const int ty = tid >> 4;   // 0..15  -> q rows ty*4..+3
    const int tx = tid & 15;   // 0..15  -> col group tx*4..+3

    // ---- load Q tile transposed ----
#pragma unroll
    for (int j = 0; j < 4; j++) {
        int f = tid + j * 256;          // float4 index 0..1023
        int r = f >> 4;                 // tile row (q) 0..63
        int c4 = (f & 15) * 4;          // d
        float4 v = *(const float4*)&qptr[(qb * 64 + r) * D_ + c4];
        Qt[(c4 + 0) * LDA + r] = v.x;
        Qt[(c4 + 1) * LDA + r] = v.y;
        Qt[(c4 + 2) * LDA + r] = v.z;
        Qt[(c4 + 3) * LDA + r] = v.w;
    }

    float mrow[4], lrow[4], o[4][4];
#pragma unroll
    for (int i = 0; i < 4; i++) {
        mrow[i] = -1e30f;
        lrow[i] = 0.0f;
#pragma unroll
        for (int j = 0; j < 4; j++) o[i][j] = 0.0f;
    }

    const int qg0 = qb * 64 + ty * 4;

    for (int kb = 0; kb <= qb; kb++) {
        __syncthreads();   // prior P*V done; safe to overwrite K/V
        // ---- load K (transposed) and V (natural) tiles ----
#pragma unroll
        for (int j = 0; j < 4; j++) {
            int f = tid + j * 256;
            int r = f >> 4;
            int c4 = (f & 15) * 4;
            float4 kv = *(const float4*)&kptr[(kb * 64 + r) * D_ + c4];
            Kt[(c4 + 0) * LDA + r] = kv.x;
            Kt[(c4 + 1) * LDA + r] = kv.y;
            Kt[(c4 + 2) * LDA + r] = kv.z;
            Kt[(c4 + 3) * LDA + r] = kv.w;
            float4 vv = *(const float4*)&vptr[(kb * 64 + r) * D_ + c4];
            *(float4*)&Vs[r * LDA + c4] = vv;
        }
        __syncthreads();

        // ---- S = Q K^T ----
        float s[4][4];
#pragma unroll
        for (int i = 0; i < 4; i++)
#pragma unroll
            for (int j = 0; j < 4; j++) s[i][j] = 0.0f;

#pragma unroll 8
        for (int d = 0; d < 64; d++) {
            float4 a = *(const float4*)&Qt[d * LDA + ty * 4];
            float4 b = *(const float4*)&Kt[d * LDA + tx * 4];
            float av[4] = {a.x, a.y, a.z, a.w};
            float bv[4] = {b.x, b.y, b.z, b.w};
#pragma unroll
            for (int i = 0; i < 4; i++)
#pragma unroll
                for (int j = 0; j < 4; j++)
                    s[i][j] = fmaf(av[i], bv[j], s[i][j]);
        }

        // ---- scale + bias + causal mask ----
        const int sg0 = kb * 64 + tx * 4;
#pragma unroll
        for (int i = 0; i < 4; i++) {
            int qg = qg0 + i;
            const float* brow = bptr + (long)qg * T_ + sg0;
#pragma unroll
            for (int j = 0; j < 4; j++) {
                float v = s[i][j] * 0.125f + brow[j];
                if (sg0 + j > qg) v = -1e30f;
                s[i][j] = v;
            }
        }

        // ---- online softmax (row stats across tx via shfl over 16 lanes) ----
#pragma unroll
        for (int i = 0; i < 4; i++) {
            float rm = fmaxf(fmaxf(s[i][0], s[i][1]), fmaxf(s[i][2], s[i][3]));
#pragma unroll
            for (int off = 1; off < 16; off <<= 1)
                rm = fmaxf(rm, __shfl_xor_sync(0xffffffffu, rm, off));
            float mnew = fmaxf(mrow[i], rm);
            float corr = __expf(mrow[i] - mnew);
            mrow[i] = mnew;
            float rs = 0.0f;
#pragma unroll
            for (int j = 0; j < 4; j++) {
                s[i][j] = __expf(s[i][j] - mnew);
                rs += s[i][j];
            }
#pragma unroll
            for (int off = 1; off < 16; off <<= 1)
                rs += __shfl_xor_sync(0xffffffffu, rs, off);
            lrow[i] = lrow[i] * corr + rs;
#pragma unroll
            for (int j = 0; j < 4; j++) o[i][j] *= corr;
        }

        // ---- write P transposed; Pt[s][q] ----
#pragma unroll
        for (int i = 0; i < 4; i++)
#pragma unroll
            for (int j = 0; j < 4; j++)
                Pt[(tx * 4 + j) * LDA + ty * 4 + i] = s[i][j];
        __syncthreads();

        // ---- O += P V ----
#pragma unroll 8
        for (int ss = 0; ss < 64; ss++) {
            float4 a = *(const float4*)&Pt[ss * LDA + ty * 4];
            float4 b = *(const float4*)&Vs[ss * LDA + tx * 4];
            float av[4] = {a.x, a.y, a.z, a.w};
            float bv[4] = {b.x, b.y, b.z, b.w};
#pragma unroll
            for (int i = 0; i < 4; i++)
#pragma unroll
                for (int j = 0; j < 4; j++)
                    o[i][j] = fmaf(av[i], bv[j], o[i][j]);
        }
    }

    // ---- epilogue: normalize, write (B,T,C) ----
    const int b = bh >> 4;
#pragma unroll
    for (int i = 0; i < 4; i++) {
        float inv = 1.0f / lrow[i];
        int t = qb * 64 + ty * 4 + i;
        float* orow = g_att + ((long)(b * T_ + t)) * C_ + h * 64 + tx * 4;
#pragma unroll
        for (int j = 0; j < 4; j++)
            orow[j] = o[i][j] * inv;
    }
}

// =================================================================
extern "C" void kernel_launch(void* const* d_in, const int* in_sizes, int n_in,
                              void* d_out, int out_size)
{
    const float* x   = (const float*)d_in[0];
    const float* Wq  = (const float*)d_in[1];
    const float* bq  = (const float*)d_in[2];
    const float* Wk  = (const float*)d_in[3];
    const float* bk  = (const float*)d_in[4];
    const float* Wv  = (const float*)d_in[5];
    const float* bv  = (const float*)d_in[6];
    const float* Wo  = (const float*)d_in[7];
    const float* bo  = (const float*)d_in[8];
    const float* rpb = (const float*)d_in[9];
    float* out = (float*)d_out;

    float *gq, *gk, *gv, *gatt;
    cudaGetSymbolAddress((void**)&gq, g_q);
    cudaGetSymbolAddress((void**)&gk, g_k);
    cudaGetSymbolAddress((void**)&gv, g_v);
    cudaGetSymbolAddress((void**)&gatt, g_att);

    cudaFuncSetAttribute(attn_kernel,
                         cudaFuncAttributeMaxDynamicSharedMemorySize, SMEM_ATTN);

    dim3 gg(C_ / BN, M_ / BM);   // (8, 64)
    gemm_xwT<<<gg, 256>>>(x, Wq, bq, gq, 1);
    gemm_xwT<<<gg, 256>>>(x, Wk, bk, gk, 1);
    gemm_xwT<<<gg, 256>>>(x, Wv, bv, gv, 1);

    attn_kernel<<<dim3(T_ / 64, B_ * H_), 256, SMEM_ATTN>>>(rpb);

    gemm_xwT<<<gg, 256>>>(gatt, Wo, bo, out, 0);
}

// round 5
// speedup vs baseline: 3.3608x; 3.3608x over previous
#include <cuda_runtime.h>
#include <cuda_bf16.h>
#include <cstdint>
#include <math.h>

#define B_   16
#define T_   512
#define C_   1024
#define H_   16
#define D_   64
#define M_   (B_ * T_)      // 8192
#define K_   C_             // 1024

// ---------------- scratch (no allocations allowed) ----------------
__device__ float g_q[B_ * H_ * T_ * D_];
__device__ float g_k[B_ * H_ * T_ * D_];
__device__ float g_v[B_ * H_ * T_ * D_];
__device__ float g_att[B_ * T_ * C_];

__device__ __nv_bfloat16 gx_hi[M_ * K_];
__device__ __nv_bfloat16 gx_lo[M_ * K_];
__device__ __nv_bfloat16 gw_hi[4 * C_ * C_];   // q,k,v,o
__device__ __nv_bfloat16 gw_lo[4 * C_ * C_];
__device__ __nv_bfloat16 ga_hi[M_ * C_];
__device__ __nv_bfloat16 ga_lo[M_ * C_];

// ================= helpers =================
__device__ __forceinline__ uint32_t smem_u32(const void* p) {
    return (uint32_t)__cvta_generic_to_shared(p);
}

#define CP_ASYNC16(dst, src) \
    asm volatile("cp.async.cg.shared.global [%0], [%1], 16;" :: "r"(dst), "l"(src) : "memory")
#define CP_COMMIT() asm volatile("cp.async.commit_group;" ::: "memory")

#define LDMX4(r, addr) \
    asm volatile("ldmatrix.sync.aligned.m8n8.x4.shared.b16 {%0,%1,%2,%3}, [%4];" \
        : "=r"((r)[0]), "=r"((r)[1]), "=r"((r)[2]), "=r"((r)[3]) : "r"(addr))

#define MMA16816(d, a, b) \
    asm volatile("mma.sync.aligned.m16n8k16.row.col.f32.bf16.bf16.f32 " \
        "{%0,%1,%2,%3}, {%4,%5,%6,%7}, {%8,%9}, {%0,%1,%2,%3};" \
        : "+f"((d)[0]), "+f"((d)[1]), "+f"((d)[2]), "+f"((d)[3]) \
        : "r"((a)[0]), "r"((a)[1]), "r"((a)[2]), "r"((a)[3]), \
          "r"((b)[0]), "r"((b)[1]))

// =================================================================
// split: fp32 -> (hi bf16, lo bf16), vectorized x4
// =================================================================
__global__ __launch_bounds__(256) void split_kernel(
    const float* __restrict__ in, __nv_bfloat16* __restrict__ hi,
    __nv_bfloat16* __restrict__ lo)
{
    int i = blockIdx.x * blockDim.x + threadIdx.x;
    float4 v = ((const float4*)in)[i];
    __nv_bfloat16 h0 = __float2bfloat16(v.x);
    __nv_bfloat16 h1 = __float2bfloat16(v.y);
    __nv_bfloat16 h2 = __float2bfloat16(v.z);
    __nv_bfloat16 h3 = __float2bfloat16(v.w);
    __nv_bfloat16 l0 = __float2bfloat16(v.x - __bfloat162float(h0));
    __nv_bfloat16 l1 = __float2bfloat16(v.y - __bfloat162float(h1));
    __nv_bfloat16 l2 = __float2bfloat16(v.z - __bfloat162float(h2));
    __nv_bfloat16 l3 = __float2bfloat16(v.w - __bfloat162float(h3));
    ((__nv_bfloat162*)hi)[2 * i + 0] = __nv_bfloat162(h0, h1);
    ((__nv_bfloat162*)hi)[2 * i + 1] = __nv_bfloat162(h2, h3);
    ((__nv_bfloat162*)lo)[2 * i + 0] = __nv_bfloat162(l0, l1);
    ((__nv_bfloat162*)lo)[2 * i + 1] = __nv_bfloat162(l2, l3);
}

// =================================================================
// mma.sync bf16x3 GEMM: out[m][n] = sum_k A[m][k]*W[n][k] + bias[n]
// CTA 128x128, BK=32 bf16, 8 warps (warp tile 64x32), 3-stage cp.async.
// smem tile rows padded to 80 B (conflict-free ldmatrix).
// =================================================================
#define NITER   32               // K / 32
#define TPITCH  80               // bytes per 32-bf16 row (64 + 16 pad)
#define TILE_B  (128 * TPITCH)   // 10240
#define STAGE_B (4 * TILE_B)     // Ahi, Alo, Bhi, Blo
#define GEMM_SMEM (3 * STAGE_B)  // 122880

__global__ __launch_bounds__(256) void gemm_tc(
    const __nv_bfloat16* __restrict__ Ahi, const __nv_bfloat16* __restrict__ Alo,
    const __nv_bfloat16* __restrict__ Bhi, const __nv_bfloat16* __restrict__ Blo,
    const float* __restrict__ bias, float* __restrict__ out, int qkv_scatter)
{
    extern __shared__ char smem[];
    const uint32_t sb = smem_u32(smem);
    const int tid  = threadIdx.x;
    const int lane = tid & 31;
    const int warp = tid >> 5;
    const int m0 = blockIdx.y * 128;
    const int n0 = blockIdx.x * 128;
    const int wm = (warp & 1) * 64;     // warp M offset
    const int wn = (warp >> 1) * 32;    // warp N offset

    const __nv_bfloat16* bases[4] = {
        Ahi + (long)m0 * K_, Alo + (long)m0 * K_,
        Bhi + (long)n0 * K_, Blo + (long)n0 * K_ };

    auto load_stage = [&](int it, int s) {
        const int k0 = it * 32;
        const uint32_t sdst = sb + s * STAGE_B;
#pragma unroll
        for (int j = 0; j < 8; j++) {
            const int idx = tid + j * 256;        // 0..2047
            const int tile = idx >> 9;            // 0..3
            const int pos = idx & 511;
            const int row = pos >> 2;             // 0..127
            const int ch  = pos & 3;              // 16B chunk
            const __nv_bfloat16* src = bases[tile] + (long)row * K_ + k0 + ch * 8;
            CP_ASYNC16(sdst + tile * TILE_B + row * TPITCH + ch * 16, src);
        }
        CP_COMMIT();
    };

    float acc[4][4][4];
#pragma unroll
    for (int mi = 0; mi < 4; mi++)
#pragma unroll
        for (int ni = 0; ni < 4; ni++)
#pragma unroll
            for (int r = 0; r < 4; r++) acc[mi][ni][r] = 0.0f;

    load_stage(0, 0);
    load_stage(1, 1);

    // ldmatrix per-lane address offsets
    const int a_row = lane & 15;               // rows 0-15
    const int a_kb  = (lane >> 4) * 16;        // k-half byte offset
    const int b_row = (lane & 7) + ((lane >> 4) << 3);
    const int b_kb  = ((lane >> 3) & 1) * 16;

    for (int it = 0; it < NITER; it++) {
        if (it < NITER - 1) asm volatile("cp.async.wait_group 1;" ::: "memory");
        else                asm volatile("cp.async.wait_group 0;" ::: "memory");
        __syncthreads();
        if (it + 2 < NITER) load_stage(it + 2, (it + 2) % 3);

        const uint32_t stg = sb + (it % 3) * STAGE_B;

#pragma unroll
        for (int kk = 0; kk < 2; kk++) {
            uint32_t ah[4][4], al[4][4];
            uint32_t bh[4][2], bl[4][2];
#pragma unroll
            for (int mi = 0; mi < 4; mi++) {
                uint32_t ad = stg + (wm + mi * 16 + a_row) * TPITCH + kk * 32 + a_kb;
                LDMX4(ah[mi], ad);
                LDMX4(al[mi], ad + TILE_B);
            }
#pragma unroll
            for (int g = 0; g < 2; g++) {
                uint32_t bd = stg + 2 * TILE_B + (wn + g * 16 + b_row) * TPITCH + kk * 32 + b_kb;
                LDMX4(((uint32_t*)bh) + 4 * g, bd);
                LDMX4(((uint32_t*)bl) + 4 * g, bd + TILE_B);
            }
#pragma unroll
            for (int mi = 0; mi < 4; mi++)
#pragma unroll
                for (int ni = 0; ni < 4; ni++) {
                    MMA16816(acc[mi][ni], ah[mi], bh[ni]);
                    MMA16816(acc[mi][ni], ah[mi], bl[ni]);
                    MMA16816(acc[mi][ni], al[mi], bh[ni]);
                }
        }
    }

    // ---- epilogue: registers -> gmem (float2, bias, optional scatter) ----
    const int r_in = lane >> 2;          // 0..7
    const int c_in = (lane & 3) * 2;     // 0,2,4,6
#pragma unroll
    for (int mi = 0; mi < 4; mi++)
#pragma unroll
        for (int ni = 0; ni < 4; ni++) {
            const int n = n0 + wn + ni * 8 + c_in;
            const float2 bz = *(const float2*)&bias[n];
#pragma unroll
            for (int half = 0; half < 2; half++) {
                const int m = m0 + wm + mi * 16 + r_in + half * 8;
                float2 v;
                v.x = acc[mi][ni][half * 2 + 0] + bz.x;
                v.y = acc[mi][ni][half * 2 + 1] + bz.y;
                if (qkv_scatter) {
                    const int bb = m >> 9, t = m & 511, h = n >> 6, d = n & 63;
                    *(float2*)&out[(((bb * H_ + h) * T_ + t) << 6) + d] = v;
                } else {
                    *(float2*)&out[(long)m * C_ + n] = v;
                }
            }
        }
}

// =================================================================
// Flash attention, fp32 (unchanged — 557us, known good).
// =================================================================
#define LDA 68
#define SMEM_ATTN (4 * 64 * LDA * (int)sizeof(float))

__global__ __launch_bounds__(256) void attn_kernel(const float* __restrict__ rpb)
{
    extern __shared__ float sm[];
    float* Qt = sm;
    float* Kt = Qt + 64 * LDA;
    float* Vs = Kt + 64 * LDA;
    float* Pt = Vs + 64 * LDA;

    const int bh = blockIdx.y;
    const int h  = bh & (H_ - 1);
    const int qb = blockIdx.x;

    const float* qptr = g_q + (long)bh * T_ * D_;
    const float* kptr = g_k + (long)bh * T_ * D_;
    const float* vptr = g_v + (long)bh * T_ * D_;
    const float* bptr = rpb + (long)h * T_ * T_;

    const int tid = threadIdx.x;
    const int ty = tid >> 4;
    const int tx = tid & 15;

#pragma unroll
    for (int j = 0; j < 4; j++) {
        int f = tid + j * 256;
        int r = f >> 4;
        int c4 = (f & 15) * 4;
        float4 v = *(const float4*)&qptr[(qb * 64 + r) * D_ + c4];
        Qt[(c4 + 0) * LDA + r] = v.x;
        Qt[(c4 + 1) * LDA + r] = v.y;
        Qt[(c4 + 2) * LDA + r] = v.z;
        Qt[(c4 + 3) * LDA + r] = v.w;
    }

    float mrow[4], lrow[4], o[4][4];
#pragma unroll
    for (int i = 0; i < 4; i++) {
        mrow[i] = -1e30f;
        lrow[i] = 0.0f;
#pragma unroll
        for (int j = 0; j < 4; j++) o[i][j] = 0.0f;
    }

    const int qg0 = qb * 64 + ty * 4;

    for (int kb = 0; kb <= qb; kb++) {
        __syncthreads();
#pragma unroll
        for (int j = 0; j < 4; j++) {
            int f = tid + j * 256;
            int r = f >> 4;
            int c4 = (f & 15) * 4;
            float4 kv = *(const float4*)&kptr[(kb * 64 + r) * D_ + c4];
            Kt[(c4 + 0) * LDA + r] = kv.x;
            Kt[(c4 + 1) * LDA + r] = kv.y;
            Kt[(c4 + 2) * LDA + r] = kv.z;
            Kt[(c4 + 3) * LDA + r] = kv.w;
            float4 vv = *(const float4*)&vptr[(kb * 64 + r) * D_ + c4];
            *(float4*)&Vs[r * LDA + c4] = vv;
        }
        __syncthreads();

        float s[4][4];
#pragma unroll
        for (int i = 0; i < 4; i++)
#pragma unroll
            for (int j = 0; j < 4; j++) s[i][j] = 0.0f;

#pragma unroll 8
        for (int d = 0; d < 64; d++) {
            float4 a = *(const float4*)&Qt[d * LDA + ty * 4];
            float4 b = *(const float4*)&Kt[d * LDA + tx * 4];
            float av[4] = {a.x, a.y, a.z, a.w};
            float bv[4] = {b.x, b.y, b.z, b.w};
#pragma unroll
            for (int i = 0; i < 4; i++)
#pragma unroll
                for (int j = 0; j < 4; j++)
                    s[i][j] = fmaf(av[i], bv[j], s[i][j]);
        }

        const int sg0 = kb * 64 + tx * 4;
#pragma unroll
        for (int i = 0; i < 4; i++) {
            int qg = qg0 + i;
            const float* brow = bptr + (long)qg * T_ + sg0;
#pragma unroll
            for (int j = 0; j < 4; j++) {
                float v = s[i][j] * 0.125f + brow[j];
                if (sg0 + j > qg) v = -1e30f;
                s[i][j] = v;
            }
        }

#pragma unroll
        for (int i = 0; i < 4; i++) {
            float rm = fmaxf(fmaxf(s[i][0], s[i][1]), fmaxf(s[i][2], s[i][3]));
#pragma unroll
            for (int off = 1; off < 16; off <<= 1)
                rm = fmaxf(rm, __shfl_xor_sync(0xffffffffu, rm, off));
            float mnew = fmaxf(mrow[i], rm);
            float corr = __expf(mrow[i] - mnew);
            mrow[i] = mnew;
            float rs = 0.0f;
#pragma unroll
            for (int j = 0; j < 4; j++) {
                s[i][j] = __expf(s[i][j] - mnew);
                rs += s[i][j];
            }
#pragma unroll
            for (int off = 1; off < 16; off <<= 1)
                rs += __shfl_xor_sync(0xffffffffu, rs, off);
            lrow[i] = lrow[i] * corr + rs;
#pragma unroll
            for (int j = 0; j < 4; j++) o[i][j] *= corr;
        }

#pragma unroll
        for (int i = 0; i < 4; i++)
#pragma unroll
            for (int j = 0; j < 4; j++)
                Pt[(tx * 4 + j) * LDA + ty * 4 + i] = s[i][j];
        __syncthreads();

#pragma unroll 8
        for (int ss = 0; ss < 64; ss++) {
            float4 a = *(const float4*)&Pt[ss * LDA + ty * 4];
            float4 b = *(const float4*)&Vs[ss * LDA + tx * 4];
            float av[4] = {a.x, a.y, a.z, a.w};
            float bv[4] = {b.x, b.y, b.z, b.w};
#pragma unroll
            for (int i = 0; i < 4; i++)
#pragma unroll
                for (int j = 0; j < 4; j++)
                    o[i][j] = fmaf(av[i], bv[j], o[i][j]);
        }
    }

    const int b = bh >> 4;
#pragma unroll
    for (int i = 0; i < 4; i++) {
        float inv = 1.0f / lrow[i];
        int t = qb * 64 + ty * 4 + i;
        float* orow = g_att + ((long)(b * T_ + t)) * C_ + h * 64 + tx * 4;
#pragma unroll
        for (int j = 0; j < 4; j++)
            orow[j] = o[i][j] * inv;
    }
}

// =================================================================
extern "C" void kernel_launch(void* const* d_in, const int* in_sizes, int n_in,
                              void* d_out, int out_size)
{
    const float* x   = (const float*)d_in[0];
    const float* Wq  = (const float*)d_in[1];
    const float* bq  = (const float*)d_in[2];
    const float* Wk  = (const float*)d_in[3];
    const float* bk  = (const float*)d_in[4];
    const float* Wv  = (const float*)d_in[5];
    const float* bv  = (const float*)d_in[6];
    const float* Wo  = (const float*)d_in[7];
    const float* bo  = (const float*)d_in[8];
    const float* rpb = (const float*)d_in[9];
    float* out = (float*)d_out;

    float *gq, *gk, *gv, *gatt;
    __nv_bfloat16 *xhi, *xlo, *whi, *wlo, *ahi, *alo;
    cudaGetSymbolAddress((void**)&gq, g_q);
    cudaGetSymbolAddress((void**)&gk, g_k);
    cudaGetSymbolAddress((void**)&gv, g_v);
    cudaGetSymbolAddress((void**)&gatt, g_att);
    cudaGetSymbolAddress((void**)&xhi, gx_hi);
    cudaGetSymbolAddress((void**)&xlo, gx_lo);
    cudaGetSymbolAddress((void**)&whi, gw_hi);
    cudaGetSymbolAddress((void**)&wlo, gw_lo);
    cudaGetSymbolAddress((void**)&ahi, ga_hi);
    cudaGetSymbolAddress((void**)&alo, ga_lo);

    cudaFuncSetAttribute(attn_kernel,
                         cudaFuncAttributeMaxDynamicSharedMemorySize, SMEM_ATTN);
    cudaFuncSetAttribute(gemm_tc,
                         cudaFuncAttributeMaxDynamicSharedMemorySize, GEMM_SMEM);

    const int WW = C_ * C_;
    split_kernel<<<(M_ * K_) / 1024, 256>>>(x, xhi, xlo);
    split_kernel<<<WW / 1024, 256>>>(Wq, whi + 0 * WW, wlo + 0 * WW);
    split_kernel<<<WW / 1024, 256>>>(Wk, whi + 1 * WW, wlo + 1 * WW);
    split_kernel<<<WW / 1024, 256>>>(Wv, whi + 2 * WW, wlo + 2 * WW);
    split_kernel<<<WW / 1024, 256>>>(Wo, whi + 3 * WW, wlo + 3 * WW);

    dim3 gg(C_ / 128, M_ / 128);        // (8, 64)
    gemm_tc<<<gg, 256, GEMM_SMEM>>>(xhi, xlo, whi + 0 * WW, wlo + 0 * WW, bq, gq, 1);
    gemm_tc<<<gg, 256, GEMM_SMEM>>>(xhi, xlo, whi + 1 * WW, wlo + 1 * WW, bk, gk, 1);
    gemm_tc<<<gg, 256, GEMM_SMEM>>>(xhi, xlo, whi + 2 * WW, wlo + 2 * WW, bv, gv, 1);

    attn_kernel<<<dim3(T_ / 64, B_ * H_), 256, SMEM_ATTN>>>(rpb);

    split_kernel<<<(M_ * C_) / 1024, 256>>>(gatt, ahi, alo);
    gemm_tc<<<gg, 256, GEMM_SMEM>>>(ahi, alo, whi + 3 * WW, wlo + 3 * WW, bo, out, 0);
}

// round 8
// speedup vs baseline: 4.0776x; 1.2133x over previous
#include <cuda_runtime.h>
#include <cuda_bf16.h>
#include <cstdint>
#include <math.h>

#define B_   16
#define T_   512
#define C_   1024
#define H_   16
#define D_   64
#define M_   (B_ * T_)      // 8192
#define K_   C_             // 1024

// ---------------- scratch (no allocations allowed) ----------------
__device__ __nv_bfloat16 gx_hi[M_ * K_];
__device__ __nv_bfloat16 gx_lo[M_ * K_];
__device__ __nv_bfloat16 gw_hi[4 * C_ * C_];   // q,k,v,o
__device__ __nv_bfloat16 gw_lo[4 * C_ * C_];
__device__ __nv_bfloat16 gq_hi[M_ * C_];       // (B,H,T,D)
__device__ __nv_bfloat16 gq_lo[M_ * C_];
__device__ __nv_bfloat16 gk_hi[M_ * C_];
__device__ __nv_bfloat16 gk_lo[M_ * C_];
__device__ __nv_bfloat16 gv_hi[M_ * C_];
__device__ __nv_bfloat16 gv_lo[M_ * C_];
__device__ __nv_bfloat16 ga_hi[M_ * C_];       // (B,T,C) attn out
__device__ __nv_bfloat16 ga_lo[M_ * C_];

// ================= helpers =================
__device__ __forceinline__ uint32_t smem_u32(const void* p) {
    return (uint32_t)__cvta_generic_to_shared(p);
}

#define CP_ASYNC16(dst, src) \
    asm volatile("cp.async.cg.shared.global [%0], [%1], 16;" :: "r"(dst), "l"(src) : "memory")
#define CP_COMMIT() asm volatile("cp.async.commit_group;" ::: "memory")

#define LDMX4(r, addr) \
    asm volatile("ldmatrix.sync.aligned.m8n8.x4.shared.b16 {%0,%1,%2,%3}, [%4];" \
        : "=r"((r)[0]), "=r"((r)[1]), "=r"((r)[2]), "=r"((r)[3]) : "r"(addr))

#define LDMX4T(r, addr) \
    asm volatile("ldmatrix.sync.aligned.m8n8.x4.trans.shared.b16 {%0,%1,%2,%3}, [%4];" \
        : "=r"((r)[0]), "=r"((r)[1]), "=r"((r)[2]), "=r"((r)[3]) : "r"(addr))

#define MMA16816(d, a, b) \
    asm volatile("mma.sync.aligned.m16n8k16.row.col.f32.bf16.bf16.f32 " \
        "{%0,%1,%2,%3}, {%4,%5,%6,%7}, {%8,%9}, {%0,%1,%2,%3};" \
        : "+f"((d)[0]), "+f"((d)[1]), "+f"((d)[2]), "+f"((d)[3]) \
        : "r"((a)[0]), "r"((a)[1]), "r"((a)[2]), "r"((a)[3]), \
          "r"((b)[0]), "r"((b)[1]))

__device__ __forceinline__ void bsplit(float x, __nv_bfloat16& h, __nv_bfloat16& l) {
    h = __float2bfloat16(x);
    l = __float2bfloat16(x - __bfloat162float(h));
}
__device__ __forceinline__ uint32_t packb2(__nv_bfloat16 a, __nv_bfloat16 b) {
    __nv_bfloat162 t(a, b);
    return *(uint32_t*)&t;
}

// =================================================================
// split: fp32 -> (hi bf16, lo bf16), vectorized x4
// =================================================================
__global__ __launch_bounds__(256) void split_kernel(
    const float* __restrict__ in, __nv_bfloat16* __restrict__ hi,
    __nv_bfloat16* __restrict__ lo)
{
    int i = blockIdx.x * blockDim.x + threadIdx.x;
    float4 v = ((const float4*)in)[i];
    __nv_bfloat16 h0, h1, h2, h3, l0, l1, l2, l3;
    bsplit(v.x, h0, l0); bsplit(v.y, h1, l1);
    bsplit(v.z, h2, l2); bsplit(v.w, h3, l3);
    ((__nv_bfloat162*)hi)[2 * i + 0] = __nv_bfloat162(h0, h1);
    ((__nv_bfloat162*)hi)[2 * i + 1] = __nv_bfloat162(h2, h3);
    ((__nv_bfloat162*)lo)[2 * i + 0] = __nv_bfloat162(l0, l1);
    ((__nv_bfloat162*)lo)[2 * i + 1] = __nv_bfloat162(l2, l3);
}

// =================================================================
// mma.sync bf16x3 GEMM. qkv_scatter: writes bf16 hi/lo to (B,H,T,D).
// else: fp32 float2 to row-major out.
// =================================================================
#define NITER   32               // K / 32
#define TPITCH  80               // bytes per 32-bf16 row (64 + 16 pad)
#define TILE_B  (128 * TPITCH)   // 10240
#define STAGE_B (4 * TILE_B)
#define GEMM_SMEM (3 * STAGE_B)  // 122880

__global__ __launch_bounds__(256) void gemm_tc(
    const __nv_bfloat16* __restrict__ Ahi, const __nv_bfloat16* __restrict__ Alo,
    const __nv_bfloat16* __restrict__ Bhi, const __nv_bfloat16* __restrict__ Blo,
    const float* __restrict__ bias, float* __restrict__ out,
    __nv_bfloat16* __restrict__ outhi, __nv_bfloat16* __restrict__ outlo,
    int qkv_scatter)
{
    extern __shared__ char smem[];
    const uint32_t sb = smem_u32(smem);
    const int tid  = threadIdx.x;
    const int lane = tid & 31;
    const int warp = tid >> 5;
    const int m0 = blockIdx.y * 128;
    const int n0 = blockIdx.x * 128;
    const int wm = (warp & 1) * 64;
    const int wn = (warp >> 1) * 32;

    const __nv_bfloat16* bases[4] = {
        Ahi + (long)m0 * K_, Alo + (long)m0 * K_,
        Bhi + (long)n0 * K_, Blo + (long)n0 * K_ };

    auto load_stage = [&](int it, int s) {
        const int k0 = it * 32;
        const uint32_t sdst = sb + s * STAGE_B;
#pragma unroll
        for (int j = 0; j < 8; j++) {
            const int idx = tid + j * 256;
            const int tile = idx >> 9;
            const int pos = idx & 511;
            const int row = pos >> 2;
            const int ch  = pos & 3;
            const __nv_bfloat16* src = bases[tile] + (long)row * K_ + k0 + ch * 8;
            CP_ASYNC16(sdst + tile * TILE_B + row * TPITCH + ch * 16, src);
        }
        CP_COMMIT();
    };

    float acc[4][4][4];
#pragma unroll
    for (int mi = 0; mi < 4; mi++)
#pragma unroll
        for (int ni = 0; ni < 4; ni++)
#pragma unroll
            for (int r = 0; r < 4; r++) acc[mi][ni][r] = 0.0f;

    load_stage(0, 0);
    load_stage(1, 1);

    const int a_row = lane & 15;
    const int a_kb  = (lane >> 4) * 16;
    const int b_row = (lane & 7) + ((lane >> 4) << 3);
    const int b_kb  = ((lane >> 3) & 1) * 16;

    for (int it = 0; it < NITER; it++) {
        if (it < NITER - 1) asm volatile("cp.async.wait_group 1;" ::: "memory");
        else                asm volatile("cp.async.wait_group 0;" ::: "memory");
        __syncthreads();
        if (it + 2 < NITER) load_stage(it + 2, (it + 2) % 3);

        const uint32_t stg = sb + (it % 3) * STAGE_B;

#pragma unroll
        for (int kk = 0; kk < 2; kk++) {
            uint32_t ah[4][4], al[4][4];
            uint32_t bh[4][2], bl[4][2];
#pragma unroll
            for (int mi = 0; mi < 4; mi++) {
                uint32_t ad = stg + (wm + mi * 16 + a_row) * TPITCH + kk * 32 + a_kb;
                LDMX4(ah[mi], ad);
                LDMX4(al[mi], ad + TILE_B);
            }
#pragma unroll
            for (int g = 0; g < 2; g++) {
                uint32_t bd = stg + 2 * TILE_B + (wn + g * 16 + b_row) * TPITCH + kk * 32 + b_kb;
                LDMX4(((uint32_t*)bh) + 4 * g, bd);
                LDMX4(((uint32_t*)bl) + 4 * g, bd + TILE_B);
            }
#pragma unroll
            for (int mi = 0; mi < 4; mi++)
#pragma unroll
                for (int ni = 0; ni < 4; ni++) {
                    MMA16816(acc[mi][ni], ah[mi], bh[ni]);
                    MMA16816(acc[mi][ni], ah[mi], bl[ni]);
                    MMA16816(acc[mi][ni], al[mi], bh[ni]);
                }
        }
    }

    const int r_in = lane >> 2;
    const int c_in = (lane & 3) * 2;
#pragma unroll
    for (int mi = 0; mi < 4; mi++)
#pragma unroll
        for (int ni = 0; ni < 4; ni++) {
            const int n = n0 + wn + ni * 8 + c_in;
            const float2 bz = *(const float2*)&bias[n];
#pragma unroll
            for (int half = 0; half < 2; half++) {
                const int m = m0 + wm + mi * 16 + r_in + half * 8;
                float vx = acc[mi][ni][half * 2 + 0] + bz.x;
                float vy = acc[mi][ni][half * 2 + 1] + bz.y;
                if (qkv_scatter) {
                    const int bb = m >> 9, t = m & 511, h = n >> 6, d = n & 63;
                    const long idx = (((long)(bb * H_ + h) * T_ + t) << 6) + d;
                    __nv_bfloat16 hx, lx, hy, ly;
                    bsplit(vx, hx, lx); bsplit(vy, hy, ly);
                    *(__nv_bfloat162*)&outhi[idx] = __nv_bfloat162(hx, hy);
                    *(__nv_bfloat162*)&outlo[idx] = __nv_bfloat162(lx, ly);
                } else {
                    float2 v; v.x = vx; v.y = vy;
                    *(float2*)&out[(long)m * C_ + n] = v;
                }
            }
        }
}

// =================================================================
// Tensor-core flash attention, bf16x3.
// CTA = (qb: 128 queries, bh). 8 warps: warp w owns q rows 16w..16w+15,
// full 64-key / 64-d width. K/V double-buffered cp.async.
// =================================================================
#define AP       144                 // smem pitch bytes for 64 bf16 row
#define QT_B     (128 * AP)          // 18432 (one of hi/lo)
#define KT_B     (64 * AP)           // 9216
#define STAGE_KV (4 * KT_B)          // Khi,Klo,Vhi,Vlo = 36864
#define SMEM_ATT (2 * QT_B + 2 * STAGE_KV)   // 110592

__global__ __launch_bounds__(256) void attn_tc(
    const __nv_bfloat16* __restrict__ qhi, const __nv_bfloat16* __restrict__ qlo,
    const __nv_bfloat16* __restrict__ khi, const __nv_bfloat16* __restrict__ klo,
    const __nv_bfloat16* __restrict__ vhi, const __nv_bfloat16* __restrict__ vlo,
    const float* __restrict__ rpb,
    __nv_bfloat16* __restrict__ outhi, __nv_bfloat16* __restrict__ outlo)
{
    extern __shared__ char smem[];
    const uint32_t sb  = smem_u32(smem);
    const uint32_t sKV = sb + 2 * QT_B;

    const int tid = threadIdx.x, lane = tid & 31, w = tid >> 5;
    const int qb = blockIdx.x, bh = blockIdx.y;
    const int h = bh & (H_ - 1), b = bh >> 4;
    const long base = (long)bh * T_ * D_;

    // ---- Q tile (hi+lo) via cp.async ----
    {
#pragma unroll
        for (int j = 0; j < 8; j++) {
            int idx = tid + j * 256;          // 0..2047
            int arr = idx >> 10;
            int pos = idx & 1023;
            int r = pos >> 3, ch = pos & 7;
            const __nv_bfloat16* src = (arr ? qlo : qhi) + base + (long)(qb * 128 + r) * D_ + ch * 8;
            CP_ASYNC16(sb + arr * QT_B + r * AP + ch * 16, src);
        }
        CP_COMMIT();
    }

    auto load_kv = [&](int kb, int s) {
        const uint32_t dst = sKV + s * STAGE_KV;
        const __nv_bfloat16* srcs[4] = {
            khi + base + (long)kb * 64 * D_, klo + base + (long)kb * 64 * D_,
            vhi + base + (long)kb * 64 * D_, vlo + base + (long)kb * 64 * D_ };
#pragma unroll
        for (int j = 0; j < 8; j++) {
            int idx = tid + j * 256;          // 0..2047
            int sub = idx >> 9;
            int pos = idx & 511;
            int r = pos >> 3, ch = pos & 7;
            CP_ASYNC16(dst + sub * KT_B + r * AP + ch * 16, srcs[sub] + (long)r * D_ + ch * 8);
        }
        CP_COMMIT();
    };

    const int nkb = 2 * qb + 2;
    load_kv(0, 0);

    float m_1 = -1e30f, m_2 = -1e30f, l_1 = 0.0f, l_2 = 0.0f;
    float o[8][4];
#pragma unroll
    for (int j = 0; j < 8; j++)
#pragma unroll
        for (int r = 0; r < 4; r++) o[j][r] = 0.0f;

    const int r1  = lane >> 2;
    const int qg1 = qb * 128 + 16 * w + r1;
    const int qg2 = qg1 + 8;
    const float* bias_base = rpb + (long)h * T_ * T_;

    const int a_row = lane & 15;
    const int a_cb  = (lane >> 4) * 16;
    const int b_row = (lane & 7) + ((lane >> 4) << 3);
    const int b_cb  = ((lane >> 3) & 1) * 16;
    const int v_row = (lane & 7) + (((lane >> 3) & 1) << 3);
    const int v_cb  = (lane >> 4) * 16;

    for (int kb = 0; kb < nkb; kb++) {
        const int s = kb & 1;
        if (kb + 1 < nkb) {
            load_kv(kb + 1, s ^ 1);
            asm volatile("cp.async.wait_group 1;" ::: "memory");
        } else {
            asm volatile("cp.async.wait_group 0;" ::: "memory");
        }
        __syncthreads();

        const bool active = (kb * 64 <= qb * 128 + 16 * w + 15);
        if (active) {
            const uint32_t stK = sKV + s * STAGE_KV;
            const uint32_t stV = stK + 2 * KT_B;

            // ---- S = Q K^T (3-term) ----
            float sc[8][4];
#pragma unroll
            for (int j = 0; j < 8; j++)
#pragma unroll
                for (int r = 0; r < 4; r++) sc[j][r] = 0.0f;

#pragma unroll
            for (int kk = 0; kk < 4; kk++) {
                uint32_t ah[4], al[4];
                const uint32_t qa = sb + (16 * w + a_row) * AP + kk * 32 + a_cb;
                LDMX4(ah, qa);
                LDMX4(al, qa + QT_B);
                uint32_t bh8[8][2], bl8[8][2];
#pragma unroll
                for (int g = 0; g < 4; g++) {
                    const uint32_t ba = stK + (g * 16 + b_row) * AP + kk * 32 + b_cb;
                    LDMX4(&bh8[2 * g][0], ba);
                    LDMX4(&bl8[2 * g][0], ba + KT_B);
                }
#pragma unroll
                for (int j = 0; j < 8; j++) {
                    MMA16816(sc[j], ah, bh8[j]);
                    MMA16816(sc[j], ah, bl8[j]);
                    MMA16816(sc[j], al, bh8[j]);
                }
            }

            // ---- scale + bias + causal mask + row max ----
            float mx1 = -1e30f, mx2 = -1e30f;
#pragma unroll
            for (int j = 0; j < 8; j++) {
                const int col = kb * 64 + 8 * j + 2 * (lane & 3);
                const float2 bb1 = *(const float2*)(bias_base + (long)qg1 * T_ + col);
                const float2 bb2 = *(const float2*)(bias_base + (long)qg2 * T_ + col);
                sc[j][0] = (col     > qg1) ? -1e30f : sc[j][0] * 0.125f + bb1.x;
                sc[j][1] = (col + 1 > qg1) ? -1e30f : sc[j][1] * 0.125f + bb1.y;
                sc[j][2] = (col     > qg2) ? -1e30f : sc[j][2] * 0.125f + bb2.x;
                sc[j][3] = (col + 1 > qg2) ? -1e30f : sc[j][3] * 0.125f + bb2.y;
                mx1 = fmaxf(mx1, fmaxf(sc[j][0], sc[j][1]));
                mx2 = fmaxf(mx2, fmaxf(sc[j][2], sc[j][3]));
            }
#pragma unroll
            for (int off = 1; off < 4; off <<= 1) {
                mx1 = fmaxf(mx1, __shfl_xor_sync(0xffffffffu, mx1, off));
                mx2 = fmaxf(mx2, __shfl_xor_sync(0xffffffffu, mx2, off));
            }
            const float mn1 = fmaxf(m_1, mx1), mn2 = fmaxf(m_2, mx2);
            const float c1 = __expf(m_1 - mn1), c2 = __expf(m_2 - mn2);
            m_1 = mn1; m_2 = mn2;
            float rs1 = 0.0f, rs2 = 0.0f;
#pragma unroll
            for (int j = 0; j < 8; j++) {
                sc[j][0] = __expf(sc[j][0] - mn1); rs1 += sc[j][0];
                sc[j][1] = __expf(sc[j][1] - mn1); rs1 += sc[j][1];
                sc[j][2] = __expf(sc[j][2] - mn2); rs2 += sc[j][2];
                sc[j][3] = __expf(sc[j][3] - mn2); rs2 += sc[j][3];
            }
#pragma unroll
            for (int off = 1; off < 4; off <<= 1) {
                rs1 += __shfl_xor_sync(0xffffffffu, rs1, off);
                rs2 += __shfl_xor_sync(0xffffffffu, rs2, off);
            }
            l_1 = l_1 * c1 + rs1;
            l_2 = l_2 * c2 + rs2;
#pragma unroll
            for (int j = 0; j < 8; j++) {
                o[j][0] *= c1; o[j][1] *= c1;
                o[j][2] *= c2; o[j][3] *= c2;
            }

            // ---- O += P V (3-term); P frags packed from accumulators ----
#pragma unroll
            for (int ks = 0; ks < 4; ks++) {
                uint32_t ph[4], pl[4];
                {
                    __nv_bfloat16 h0, l0, h1, l1;
#pragma unroll
                    for (int q = 0; q < 2; q++) {
                        const float* p = sc[2 * ks + q];
                        bsplit(p[0], h0, l0); bsplit(p[1], h1, l1);
                        ph[2 * q]     = packb2(h0, h1);
                        pl[2 * q]     = packb2(l0, l1);
                        bsplit(p[2], h0, l0); bsplit(p[3], h1, l1);
                        ph[2 * q + 1] = packb2(h0, h1);
                        pl[2 * q + 1] = packb2(l0, l1);
                    }
                }
                uint32_t vh8[8][2], vl8[8][2];
#pragma unroll
                for (int g = 0; g < 4; g++) {
                    const uint32_t va = stV + (ks * 16 + v_row) * AP + g * 32 + v_cb;
                    LDMX4T(&vh8[2 * g][0], va);
                    LDMX4T(&vl8[2 * g][0], va + KT_B);
                }
#pragma unroll
                for (int j = 0; j < 8; j++) {
                    MMA16816(o[j], ph, vh8[j]);
                    MMA16816(o[j], ph, vl8[j]);
                    MMA16816(o[j], pl, vh8[j]);
                }
            }
        }
        __syncthreads();
    }

    // ---- epilogue: normalize, split hi/lo, write (B,T,C) ----
    const float inv1 = 1.0f / l_1;
    const float inv2 = 1.0f / l_2;
    const int t1 = qb * 128 + 16 * w + r1;
    const int d0 = 2 * (lane & 3);
#pragma unroll
    for (int j = 0; j < 8; j++) {
        const int d = 8 * j + d0;
        __nv_bfloat16 h0, l0, h1, l1;
        bsplit(o[j][0] * inv1, h0, l0);
        bsplit(o[j][1] * inv1, h1, l1);
        const long i1 = (long)(b * T_ + t1) * C_ + h * 64 + d;
        *(__nv_bfloat162*)&outhi[i1] = __nv_bfloat162(h0, h1);
        *(__nv_bfloat162*)&outlo[i1] = __nv_bfloat162(l0, l1);
        bsplit(o[j][2] * inv2, h0, l0);
        bsplit(o[j][3] * inv2, h1, l1);
        const long i2 = (long)(b * T_ + t1 + 8) * C_ + h * 64 + d;
        *(__nv_bfloat162*)&outhi[i2] = __nv_bfloat162(h0, h1);
        *(__nv_bfloat162*)&outlo[i2] = __nv_bfloat162(l0, l1);
    }
}

// =================================================================
extern "C" void kernel_launch(void* const* d_in, const int* in_sizes, int n_in,
                              void* d_out, int out_size)
{
    const float* x   = (const float*)d_in[0];
    const float* Wq  = (const float*)d_in[1];
    const float* bq  = (const float*)d_in[2];
    const float* Wk  = (const float*)d_in[3];
    const float* bk  = (const float*)d_in[4];
    const float* Wv  = (const float*)d_in[5];
    const float* bv  = (const float*)d_in[6];
    const float* Wo  = (const float*)d_in[7];
    const float* bo  = (const float*)d_in[8];
    const float* rpb = (const float*)d_in[9];
    float* out = (float*)d_out;

    __nv_bfloat16 *xhi, *xlo, *whi, *wlo;
    __nv_bfloat16 *qhi, *qlo, *khi, *klo, *vhi, *vlo, *ahi, *alo;
    cudaGetSymbolAddress((void**)&xhi, gx_hi);
    cudaGetSymbolAddress((void**)&xlo, gx_lo);
    cudaGetSymbolAddress((void**)&whi, gw_hi);
    cudaGetSymbolAddress((void**)&wlo, gw_lo);
    cudaGetSymbolAddress((void**)&qhi, gq_hi);
    cudaGetSymbolAddress((void**)&qlo, gq_lo);
    cudaGetSymbolAddress((void**)&khi, gk_hi);
    cudaGetSymbolAddress((void**)&klo, gk_lo);
    cudaGetSymbolAddress((void**)&vhi, gv_hi);
    cudaGetSymbolAddress((void**)&vlo, gv_lo);
    cudaGetSymbolAddress((void**)&ahi, ga_hi);
    cudaGetSymbolAddress((void**)&alo, ga_lo);

    cudaFuncSetAttribute(gemm_tc,
                         cudaFuncAttributeMaxDynamicSharedMemorySize, GEMM_SMEM);
    cudaFuncSetAttribute(attn_tc,
                         cudaFuncAttributeMaxDynamicSharedMemorySize, SMEM_ATT);

    const int WW = C_ * C_;
    split_kernel<<<(M_ * K_) / 1024, 256>>>(x, xhi, xlo);
    split_kernel<<<WW / 1024, 256>>>(Wq, whi + 0 * WW, wlo + 0 * WW);
    split_kernel<<<WW / 1024, 256>>>(Wk, whi + 1 * WW, wlo + 1 * WW);
    split_kernel<<<WW / 1024, 256>>>(Wv, whi + 2 * WW, wlo + 2 * WW);
    split_kernel<<<WW / 1024, 256>>>(Wo, whi + 3 * WW, wlo + 3 * WW);

    dim3 gg(C_ / 128, M_ / 128);        // (8, 64)
    gemm_tc<<<gg, 256, GEMM_SMEM>>>(xhi, xlo, whi + 0 * WW, wlo + 0 * WW, bq,
                                    nullptr, qhi, qlo, 1);
    gemm_tc<<<gg, 256, GEMM_SMEM>>>(xhi, xlo, whi + 1 * WW, wlo + 1 * WW, bk,
                                    nullptr, khi, klo, 1);
    gemm_tc<<<gg, 256, GEMM_SMEM>>>(xhi, xlo, whi + 2 * WW, wlo + 2 * WW, bv,
                                    nullptr, vhi, vlo, 1);

    attn_tc<<<dim3(T_ / 128, B_ * H_), 256, SMEM_ATT>>>(
        qhi, qlo, khi, klo, vhi, vlo, rpb, ahi, alo);

    gemm_tc<<<gg, 256, GEMM_SMEM>>>(ahi, alo, whi + 3 * WW, wlo + 3 * WW, bo,
                                    out, nullptr, nullptr, 0);
}